// round 1
// baseline (speedup 1.0000x reference)
#include <cuda_runtime.h>
#include <cstdint>
#include <cstddef>

#define NBATCH 8
#define CFEAT  256
#define NGROUP 8
#define CPG    32
#define NTOT   21760
#define KTOP   100
#define NLEV   4
#define GNEPS  1e-5f

// ---------------- device scratch (static allocation: no cudaMalloc allowed) ----------------
__device__ float   g_h[(size_t)NBATCH * CFEAT * NTOT];   // 178 MB hidden activations
__device__ float   g_logits[NBATCH * NTOT];
__device__ double2 g_part1[NLEV * NBATCH * NGROUP * 8];  // per-chunk partial (sum, sumsq)
__device__ double2 g_part2[NLEV * NBATCH * NGROUP * 8];
__device__ float   g_a1[NLEV * NBATCH * CFEAT];
__device__ float   g_d1[NLEV * NBATCH * CFEAT];
__device__ float   g_a2[NLEV * NBATCH * CFEAT];
__device__ float   g_d2[NLEV * NBATCH * CFEAT];

// ---------------- stage 1/3: groupnorm partial stats (deterministic, no atomics) ----------------
// one block per (b, g, chunk); reduces 32 channels x chunk columns
__global__ void stats_kernel(const float* __restrict__ src, int rowStride, int colOff,
                             int L, double2* __restrict__ part, int partBase)
{
    const int b = blockIdx.z, g = blockIdx.y, ch = blockIdx.x;
    const int tid = threadIdx.x;
    const int l0 = ch * 2048;
    const int l1 = min(l0 + 2048, L);

    double s = 0.0, ss = 0.0;
    for (int c = 0; c < CPG; ++c) {
        const float* row = src + (size_t)(b * CFEAT + g * CPG + c) * rowStride + colOff;
        for (int i = l0 + tid; i < l1; i += 256) {
            double v = (double)row[i];
            s += v; ss += v * v;
        }
    }
    __shared__ double shs[256], shq[256];
    shs[tid] = s; shq[tid] = ss;
    __syncthreads();
    for (int st = 128; st > 0; st >>= 1) {
        if (tid < st) { shs[tid] += shs[tid + st]; shq[tid] += shq[tid + st]; }
        __syncthreads();
    }
    if (tid == 0) part[partBase + (b * NGROUP + g) * 8 + ch] = make_double2(shs[0], shq[0]);
}

// finalize: reduce partials (fixed order), emit per-channel fused affine a*x + d
__global__ void finalize_kernel(const double2* __restrict__ part,
                                const float* __restrict__ scale, const float* __restrict__ bias,
                                float* __restrict__ aOut, float* __restrict__ dOut)
{
    const int idx = blockIdx.x;                 // lev*64 + b*8 + g
    const int lev = idx >> 6, b = (idx >> 3) & 7, g = idx & 7;
    const int Ls[4] = {16384, 4096, 1024, 256};
    const int L = Ls[lev];
    const int nch = (L + 2047) / 2048;

    double s = 0.0, ss = 0.0;
    for (int ch = 0; ch < nch; ++ch) {
        double2 p = part[lev * 512 + (b * NGROUP + g) * 8 + ch];
        s += p.x; ss += p.y;
    }
    const double cnt = 32.0 * (double)L;
    const double mu = s / cnt;
    const float var = (float)(ss / cnt - mu * mu);
    const float rinv = rsqrtf(var + GNEPS);

    const int c = g * CPG + threadIdx.x;        // 32 threads
    const float a = scale[c] * rinv;
    aOut[(lev * NBATCH + b) * CFEAT + c] = a;
    dOut[(lev * NBATCH + b) * CFEAT + c] = bias[c] - (float)mu * a;
}

// ---------------- stage 2: fused GN1-affine + ReLU + 256x256 GEMM + bias ----------------
// classic 128x128x8 double-buffered SGEMM, 256 threads, 8x8 microtile
__global__ __launch_bounds__(256, 2)
void gemm1_kernel(const float* __restrict__ x, const float* __restrict__ W1,
                  const float* __restrict__ b1,
                  const float* __restrict__ a1, const float* __restrict__ d1,
                  float* __restrict__ hbase, int L, int colOff)
{
    __shared__ float As[2][8][128];
    __shared__ float Bs[2][8][128];
    __shared__ float sa[256], sd[256];

    const int tid = threadIdx.x;
    const int b  = blockIdx.z;
    const int om = blockIdx.y * 128;
    const int ln = blockIdx.x * 128;

    sa[tid] = a1[b * 256 + tid];
    sd[tid] = d1[b * 256 + tid];

    const float* xb = x + (size_t)b * 256 * L;

    const int am = tid >> 1;              // 0..127  (A row within tile)
    const int ak = (tid & 1) * 4;         // 0 or 4  (A k sub-offset)
    const int bk = tid >> 5;              // 0..7    (B k row)
    const int bn = (tid & 31) * 4;        // 0..124  (B col)
    const int ty = tid >> 4;              // 0..15
    const int tx = tid & 15;              // 0..15

    float acc[8][8];
#pragma unroll
    for (int i = 0; i < 8; ++i)
#pragma unroll
        for (int j = 0; j < 8; ++j) acc[i][j] = 0.f;

    __syncthreads();  // sa/sd ready

    // preload tile 0
    {
        float4 w = *(const float4*)&W1[(om + am) * 256 + ak];
        float4 v = *(const float4*)&xb[(size_t)bk * L + ln + bn];
        float a = sa[bk], d = sd[bk];
        As[0][ak + 0][am] = w.x; As[0][ak + 1][am] = w.y;
        As[0][ak + 2][am] = w.z; As[0][ak + 3][am] = w.w;
        Bs[0][bk][bn + 0] = fmaxf(fmaf(a, v.x, d), 0.f);
        Bs[0][bk][bn + 1] = fmaxf(fmaf(a, v.y, d), 0.f);
        Bs[0][bk][bn + 2] = fmaxf(fmaf(a, v.z, d), 0.f);
        Bs[0][bk][bn + 3] = fmaxf(fmaf(a, v.w, d), 0.f);
    }
    __syncthreads();

    for (int kt = 0; kt < 32; ++kt) {
        const int cur = kt & 1;
        float4 wn, vn; float an = 0.f, dn = 0.f;
        if (kt < 31) {
            const int kc = (kt + 1) * 8;
            wn = *(const float4*)&W1[(om + am) * 256 + kc + ak];
            vn = *(const float4*)&xb[(size_t)(kc + bk) * L + ln + bn];
            an = sa[kc + bk]; dn = sd[kc + bk];
        }
#pragma unroll
        for (int kk = 0; kk < 8; ++kk) {
            float4 a0 = *(const float4*)&As[cur][kk][ty * 4];
            float4 a1v = *(const float4*)&As[cur][kk][64 + ty * 4];
            float4 b0 = *(const float4*)&Bs[cur][kk][tx * 4];
            float4 b1v = *(const float4*)&Bs[cur][kk][64 + tx * 4];
            float av[8] = {a0.x, a0.y, a0.z, a0.w, a1v.x, a1v.y, a1v.z, a1v.w};
            float bv[8] = {b0.x, b0.y, b0.z, b0.w, b1v.x, b1v.y, b1v.z, b1v.w};
#pragma unroll
            for (int i = 0; i < 8; ++i)
#pragma unroll
                for (int j = 0; j < 8; ++j)
                    acc[i][j] = fmaf(av[i], bv[j], acc[i][j]);
        }
        if (kt < 31) {
            const int nxt = cur ^ 1;
            As[nxt][ak + 0][am] = wn.x; As[nxt][ak + 1][am] = wn.y;
            As[nxt][ak + 2][am] = wn.z; As[nxt][ak + 3][am] = wn.w;
            Bs[nxt][bk][bn + 0] = fmaxf(fmaf(an, vn.x, dn), 0.f);
            Bs[nxt][bk][bn + 1] = fmaxf(fmaf(an, vn.y, dn), 0.f);
            Bs[nxt][bk][bn + 2] = fmaxf(fmaf(an, vn.z, dn), 0.f);
            Bs[nxt][bk][bn + 3] = fmaxf(fmaf(an, vn.w, dn), 0.f);
        }
        __syncthreads();
    }

    // epilogue: + b1[o], write h
    float* hrow = hbase + ((size_t)(b * 256 + om)) * NTOT + colOff + ln;
#pragma unroll
    for (int i = 0; i < 8; ++i) {
        const int m = (i < 4) ? (ty * 4 + i) : (64 + ty * 4 + i - 4);
        const float bb = b1[om + m];
        float4 v0 = make_float4(acc[i][0] + bb, acc[i][1] + bb, acc[i][2] + bb, acc[i][3] + bb);
        float4 v1 = make_float4(acc[i][4] + bb, acc[i][5] + bb, acc[i][6] + bb, acc[i][7] + bb);
        *(float4*)&hrow[(size_t)m * NTOT + tx * 4] = v0;
        *(float4*)&hrow[(size_t)m * NTOT + 64 + tx * 4] = v1;
    }
}

// ---------------- stage 4: fused GN2-affine + ReLU + W2 dot + b2 -> logits ----------------
__global__ __launch_bounds__(256)
void logits_kernel(const float* __restrict__ h, const float* __restrict__ a2,
                   const float* __restrict__ d2, const float* __restrict__ W2,
                   const float* __restrict__ b2, float* __restrict__ logits,
                   float* __restrict__ outLog, int colOff)
{
    __shared__ float sa[256], sd[256], sw[256];
    const int tid = threadIdx.x;
    const int b = blockIdx.y;
    sa[tid] = a2[b * 256 + tid];
    sd[tid] = d2[b * 256 + tid];
    sw[tid] = W2[tid];
    __syncthreads();

    const int pos = colOff + blockIdx.x * 256 + tid;
    const float* hp = h + (size_t)b * 256 * NTOT + pos;
    float acc = b2[0];
#pragma unroll 4
    for (int c = 0; c < 256; ++c) {
        float v = hp[(size_t)c * NTOT];
        acc = fmaf(sw[c], fmaxf(fmaf(sa[c], v, sd[c]), 0.f), acc);
    }
    logits[b * NTOT + pos] = acc;
    if (outLog) outLog[b * NTOT + pos] = acc;
}

// ---------------- stage 5: top-100 per batch, (value desc, index asc) tie-break ----------------
__global__ __launch_bounds__(1024)
void topk_kernel(const float* __restrict__ logits, float* __restrict__ outF, int* __restrict__ outI)
{
    extern __shared__ float sv[];   // NTOT floats
    __shared__ float rv[1024];
    __shared__ int   ri[1024];
    const int b = blockIdx.x, tid = threadIdx.x;
    const float NEGINF = __int_as_float(0xff800000);

    for (int i = tid; i < NTOT; i += 1024) sv[i] = logits[b * NTOT + i];
    __syncthreads();

    for (int k = 0; k < KTOP; ++k) {
        float bv = NEGINF; int bi = 0x7fffffff;
        for (int i = tid; i < NTOT; i += 1024) {
            float v = sv[i];
            if (v > bv || (v == bv && i < bi)) { bv = v; bi = i; }
        }
        rv[tid] = bv; ri[tid] = bi;
        __syncthreads();
        for (int st = 512; st > 0; st >>= 1) {
            if (tid < st) {
                float ov = rv[tid + st]; int oi = ri[tid + st];
                if (ov > rv[tid] || (ov == rv[tid] && oi < ri[tid])) { rv[tid] = ov; ri[tid] = oi; }
            }
            __syncthreads();
        }
        if (tid == 0) {
            const int w = ri[0];
            if (outF) outF[b * KTOP + k] = (float)w;
            if (outI) outI[b * KTOP + k] = w;
            sv[w] = NEGINF;
        }
        __syncthreads();
    }
}

// ---------------- host launcher ----------------
extern "C" void kernel_launch(void* const* d_in, const int* in_sizes, int n_in,
                              void* d_out, int out_size)
{
    (void)in_sizes; (void)n_in;
    const float* xs[4] = {(const float*)d_in[0], (const float*)d_in[1],
                          (const float*)d_in[2], (const float*)d_in[3]};
    const float* gn1_scale = (const float*)d_in[4];
    const float* gn1_bias  = (const float*)d_in[5];
    const float* W1        = (const float*)d_in[6];
    const float* b1        = (const float*)d_in[7];
    const float* gn2_scale = (const float*)d_in[8];
    const float* gn2_bias  = (const float*)d_in[9];
    const float* W2        = (const float*)d_in[10];
    const float* b2        = (const float*)d_in[11];

    const int Ls[4]   = {16384, 4096, 1024, 256};
    const int offs[4] = {0, 16384, 20480, 21504};

    void* tmp;
    cudaGetSymbolAddress(&tmp, g_h);      float*   p_h     = (float*)tmp;
    cudaGetSymbolAddress(&tmp, g_logits); float*   p_log   = (float*)tmp;
    cudaGetSymbolAddress(&tmp, g_part1);  double2* p_part1 = (double2*)tmp;
    cudaGetSymbolAddress(&tmp, g_part2);  double2* p_part2 = (double2*)tmp;
    cudaGetSymbolAddress(&tmp, g_a1);     float*   p_a1    = (float*)tmp;
    cudaGetSymbolAddress(&tmp, g_d1);     float*   p_d1    = (float*)tmp;
    cudaGetSymbolAddress(&tmp, g_a2);     float*   p_a2    = (float*)tmp;
    cudaGetSymbolAddress(&tmp, g_d2);     float*   p_d2    = (float*)tmp;

    // output layout: tuple (sample_ids[8,100], logits[8,21760]) flattened
    float* outF   = (float*)d_out;
    float* outLog = nullptr;
    float* outIdF = nullptr;
    int*   outIdI = nullptr;
    const int NIDS = NBATCH * KTOP;            // 800
    const int NLOG = NBATCH * NTOT;            // 174080
    if (out_size >= NIDS + NLOG)      { outIdF = outF; outLog = outF + NIDS; }
    else if (out_size == NLOG)        { outLog = outF; }
    else if (out_size == NIDS)        { outIdI = (int*)d_out; }
    else                              { outIdF = outF; if (out_size > NIDS) outLog = outF + NIDS; }

    // 1) GN1 stats
    for (int lev = 0; lev < 4; ++lev) {
        const int nch = (Ls[lev] + 2047) / 2048;
        stats_kernel<<<dim3(nch, NGROUP, NBATCH), 256>>>(xs[lev], Ls[lev], 0, Ls[lev],
                                                          p_part1, lev * 512);
    }
    finalize_kernel<<<NLEV * NBATCH * NGROUP, 32>>>(p_part1, gn1_scale, gn1_bias, p_a1, p_d1);

    // 2) fused GN1+ReLU+GEMM1+bias -> h
    for (int lev = 0; lev < 4; ++lev) {
        gemm1_kernel<<<dim3(Ls[lev] / 128, 2, NBATCH), 256>>>(
            xs[lev], W1, b1, p_a1 + lev * NBATCH * CFEAT, p_d1 + lev * NBATCH * CFEAT,
            p_h, Ls[lev], offs[lev]);
    }

    // 3) GN2 stats on h
    for (int lev = 0; lev < 4; ++lev) {
        const int nch = (Ls[lev] + 2047) / 2048;
        stats_kernel<<<dim3(nch, NGROUP, NBATCH), 256>>>(p_h, NTOT, offs[lev], Ls[lev],
                                                          p_part2, lev * 512);
    }
    finalize_kernel<<<NLEV * NBATCH * NGROUP, 32>>>(p_part2, gn2_scale, gn2_bias, p_a2, p_d2);

    // 4) logits
    for (int lev = 0; lev < 4; ++lev) {
        logits_kernel<<<dim3(Ls[lev] / 256, NBATCH), 256>>>(
            p_h, p_a2 + lev * NBATCH * CFEAT, p_d2 + lev * NBATCH * CFEAT,
            W2, b2, p_log, outLog, offs[lev]);
    }

    // 5) top-k
    cudaFuncSetAttribute(topk_kernel, cudaFuncAttributeMaxDynamicSharedMemorySize, NTOT * 4);
    topk_kernel<<<NBATCH, 1024, NTOT * 4>>>(p_log, outIdF, outIdI);
}

// round 2
// speedup vs baseline: 1.2228x; 1.2228x over previous
#include <cuda_runtime.h>
#include <cstdint>
#include <cstddef>

#define NBATCH 8
#define CFEAT  256
#define NGROUP 8
#define CPG    32
#define NTOT   21760
#define KTOP   100
#define NLEV   4
#define GNEPS  1e-5f
#define NCB    170          // total 128-wide column blocks across all levels

// ---------------- device scratch ----------------
__device__ float   g_h[(size_t)NBATCH * CFEAT * NTOT];
__device__ float   g_logits[NBATCH * NTOT];
__device__ double2 g_part1[NLEV * NBATCH * NGROUP * 8];
__device__ double2 g_part2[NBATCH * NGROUP * NCB];       // per (b,g,colblock)
__device__ float   g_a1[NLEV * NBATCH * CFEAT];
__device__ float   g_d1[NLEV * NBATCH * CFEAT];
__device__ float   g_a2[NLEV * NBATCH * CFEAT];
__device__ float   g_d2[NLEV * NBATCH * CFEAT];

// ---------------- packed f32x2 helpers ----------------
__device__ __forceinline__ void ffma2(unsigned long long& d, unsigned long long a,
                                      unsigned long long b) {
    asm("fma.rn.f32x2 %0, %1, %2, %0;" : "+l"(d) : "l"(a), "l"(b));
}
__device__ __forceinline__ unsigned long long pack2(float x, float y) {
    unsigned long long r;
    asm("mov.b64 %0, {%1,%2};" : "=l"(r) : "f"(x), "f"(y));
    return r;
}
__device__ __forceinline__ float2 unpack2(unsigned long long v) {
    float2 r;
    asm("mov.b64 {%0,%1}, %2;" : "=f"(r.x), "=f"(r.y) : "l"(v));
    return r;
}

// ---------------- GN1 stats: coalesced float4, fp32 partials, shuffle reduce ----------------
__global__ void stats_kernel(const float* __restrict__ src, int L, int chunkL,
                             double2* __restrict__ part, int partBase)
{
    const int b = blockIdx.z, g = blockIdx.y, ch = blockIdx.x;
    const int tid = threadIdx.x;
    const int q0 = (ch * chunkL) >> 2;
    const int q1 = min((ch + 1) * chunkL, L) >> 2;

    float s = 0.f, q = 0.f;
    for (int c = 0; c < CPG; ++c) {
        const float4* row = (const float4*)(src + (size_t)(b * CFEAT + g * CPG + c) * L);
        for (int i = q0 + tid; i < q1; i += 256) {
            float4 v = row[i];
            s += (v.x + v.y) + (v.z + v.w);
            q += (v.x * v.x + v.y * v.y) + (v.z * v.z + v.w * v.w);
        }
    }
#pragma unroll
    for (int off = 16; off; off >>= 1) {
        s += __shfl_down_sync(0xffffffffu, s, off);
        q += __shfl_down_sync(0xffffffffu, q, off);
    }
    __shared__ float ws[8], wq[8];
    if ((tid & 31) == 0) { ws[tid >> 5] = s; wq[tid >> 5] = q; }
    __syncthreads();
    if (tid == 0) {
        double S = 0.0, Q = 0.0;
        for (int w = 0; w < 8; ++w) { S += (double)ws[w]; Q += (double)wq[w]; }
        part[partBase + (b * NGROUP + g) * 8 + ch] = make_double2(S, Q);
    }
}

__global__ void finalize1_kernel(const double2* __restrict__ part,
                                 const float* __restrict__ scale, const float* __restrict__ bias,
                                 float* __restrict__ aOut, float* __restrict__ dOut)
{
    const int idx = blockIdx.x;                 // lev*64 + b*8 + g
    const int lev = idx >> 6, b = (idx >> 3) & 7, g = idx & 7;
    const int Ls[4] = {16384, 4096, 1024, 256};
    const int L = Ls[lev];
    const int nch = (L + 2047) / 2048;

    double s = 0.0, ss = 0.0;
    for (int ch = 0; ch < nch; ++ch) {
        double2 p = part[lev * 512 + (b * NGROUP + g) * 8 + ch];
        s += p.x; ss += p.y;
    }
    const double cnt = 32.0 * (double)L;
    const double mu = s / cnt;
    const float var = (float)(ss / cnt - mu * mu);
    const float rinv = rsqrtf(var + GNEPS);

    const int c = g * CPG + threadIdx.x;
    const float a = scale[c] * rinv;
    aOut[(lev * NBATCH + b) * CFEAT + c] = a;
    dOut[(lev * NBATCH + b) * CFEAT + c] = bias[c] - (float)mu * a;
}

// ---------------- stage 2: fused GN1+ReLU + GEMM (FFMA2) + bias + GN2 partial stats ----------------
__global__ __launch_bounds__(256, 2)
void gemm1_kernel(const float* __restrict__ x, const float* __restrict__ W1,
                  const float* __restrict__ b1,
                  const float* __restrict__ a1, const float* __restrict__ d1,
                  float* __restrict__ hbase, double2* __restrict__ part2,
                  int L, int colOff, int colBase)
{
    __shared__ unsigned long long As2[2][8][128];   // A value duplicated into both halves
    __shared__ float Bs[2][8][128];
    __shared__ float sa[256], sd[256];
    __shared__ float r0s[256], r0q[256], r1s[256], r1q[256];

    const int tid = threadIdx.x;
    const int b   = blockIdx.z;
    const int om2 = blockIdx.y;             // 0 or 1
    const int om  = om2 * 128;
    const int ln  = blockIdx.x * 128;

    sa[tid] = a1[b * 256 + tid];
    sd[tid] = d1[b * 256 + tid];

    const float* xb = x + (size_t)b * 256 * L;

    const int am = tid >> 1;
    const int ak = (tid & 1) * 4;
    const int bk = tid >> 5;
    const int bn = (tid & 31) * 4;
    const int ty = tid >> 4;
    const int tx = tid & 15;

    unsigned long long acc[8][4];
#pragma unroll
    for (int i = 0; i < 8; ++i)
#pragma unroll
        for (int j = 0; j < 4; ++j) acc[i][j] = 0ull;

    __syncthreads();

    // preload tile 0
    {
        float4 w = *(const float4*)&W1[(om + am) * 256 + ak];
        float4 v = *(const float4*)&xb[(size_t)bk * L + ln + bn];
        float a = sa[bk], d = sd[bk];
        As2[0][ak + 0][am] = pack2(w.x, w.x);
        As2[0][ak + 1][am] = pack2(w.y, w.y);
        As2[0][ak + 2][am] = pack2(w.z, w.z);
        As2[0][ak + 3][am] = pack2(w.w, w.w);
        Bs[0][bk][bn + 0] = fmaxf(fmaf(a, v.x, d), 0.f);
        Bs[0][bk][bn + 1] = fmaxf(fmaf(a, v.y, d), 0.f);
        Bs[0][bk][bn + 2] = fmaxf(fmaf(a, v.z, d), 0.f);
        Bs[0][bk][bn + 3] = fmaxf(fmaf(a, v.w, d), 0.f);
    }
    __syncthreads();

    for (int kt = 0; kt < 32; ++kt) {
        const int cur = kt & 1;
        float4 wn, vn; float an = 0.f, dn = 0.f;
        if (kt < 31) {
            const int kc = (kt + 1) * 8;
            wn = *(const float4*)&W1[(om + am) * 256 + kc + ak];
            vn = *(const float4*)&xb[(size_t)(kc + bk) * L + ln + bn];
            an = sa[kc + bk]; dn = sd[kc + bk];
        }
#pragma unroll
        for (int kk = 0; kk < 8; ++kk) {
            ulonglong2 b01 = *reinterpret_cast<const ulonglong2*>(&Bs[cur][kk][tx * 4]);
            ulonglong2 b23 = *reinterpret_cast<const ulonglong2*>(&Bs[cur][kk][64 + tx * 4]);
            unsigned long long bv[4] = {b01.x, b01.y, b23.x, b23.y};
            ulonglong2 a01 = *reinterpret_cast<const ulonglong2*>(&As2[cur][kk][ty * 4]);
            ulonglong2 a23 = *reinterpret_cast<const ulonglong2*>(&As2[cur][kk][ty * 4 + 2]);
            ulonglong2 a45 = *reinterpret_cast<const ulonglong2*>(&As2[cur][kk][64 + ty * 4]);
            ulonglong2 a67 = *reinterpret_cast<const ulonglong2*>(&As2[cur][kk][64 + ty * 4 + 2]);
            unsigned long long av[8] = {a01.x, a01.y, a23.x, a23.y, a45.x, a45.y, a67.x, a67.y};
#pragma unroll
            for (int i = 0; i < 8; ++i)
#pragma unroll
                for (int j = 0; j < 4; ++j)
                    ffma2(acc[i][j], av[i], bv[j]);
        }
        if (kt < 31) {
            const int nxt = cur ^ 1;
            As2[nxt][ak + 0][am] = pack2(wn.x, wn.x);
            As2[nxt][ak + 1][am] = pack2(wn.y, wn.y);
            As2[nxt][ak + 2][am] = pack2(wn.z, wn.z);
            As2[nxt][ak + 3][am] = pack2(wn.w, wn.w);
            Bs[nxt][bk][bn + 0] = fmaxf(fmaf(an, vn.x, dn), 0.f);
            Bs[nxt][bk][bn + 1] = fmaxf(fmaf(an, vn.y, dn), 0.f);
            Bs[nxt][bk][bn + 2] = fmaxf(fmaf(an, vn.z, dn), 0.f);
            Bs[nxt][bk][bn + 3] = fmaxf(fmaf(an, vn.w, dn), 0.f);
        }
        __syncthreads();
    }

    // epilogue: +bias, write h, accumulate per-group stats (rows i<4 -> group ty/8; i>=4 -> 2+ty/8)
    float* hrow = hbase + ((size_t)(b * 256 + om)) * NTOT + colOff + ln;
    float s0 = 0.f, q0 = 0.f, s1 = 0.f, q1 = 0.f;
#pragma unroll
    for (int i = 0; i < 8; ++i) {
        const int m = (i < 4) ? (ty * 4 + i) : (64 + ty * 4 + i - 4);
        const float bb = b1[om + m];
        float2 p0 = unpack2(acc[i][0]);
        float2 p1 = unpack2(acc[i][1]);
        float2 p2 = unpack2(acc[i][2]);
        float2 p3 = unpack2(acc[i][3]);
        float v[8] = {p0.x + bb, p0.y + bb, p1.x + bb, p1.y + bb,
                      p2.x + bb, p2.y + bb, p3.x + bb, p3.y + bb};
        *(float4*)&hrow[(size_t)m * NTOT + tx * 4]      = make_float4(v[0], v[1], v[2], v[3]);
        *(float4*)&hrow[(size_t)m * NTOT + 64 + tx * 4] = make_float4(v[4], v[5], v[6], v[7]);
        float ls = 0.f, lq = 0.f;
#pragma unroll
        for (int j = 0; j < 8; ++j) { ls += v[j]; lq += v[j] * v[j]; }
        if (i < 4) { s0 += ls; q0 += lq; } else { s1 += ls; q1 += lq; }
    }
    r0s[tid] = s0; r0q[tid] = q0; r1s[tid] = s1; r1q[tid] = q1;
    __syncthreads();
    // reduce within each half of 128 threads (halves correspond to different groups)
    for (int st = 64; st > 0; st >>= 1) {
        if ((tid & 127) < st) {
            r0s[tid] += r0s[tid + st]; r0q[tid] += r0q[tid + st];
            r1s[tid] += r1s[tid + st]; r1q[tid] += r1q[tid + st];
        }
        __syncthreads();
    }
    if ((tid & 127) == 0) {
        const int half = tid >> 7;                  // 0 or 1
        const int cb = colBase + blockIdx.x;
        const int gA = om2 * 4 + half;              // rows 0..63 of tile
        const int gB = om2 * 4 + 2 + half;          // rows 64..127
        part2[(size_t)(b * NGROUP + gA) * NCB + cb] = make_double2((double)r0s[tid], (double)r0q[tid]);
        part2[(size_t)(b * NGROUP + gB) * NCB + cb] = make_double2((double)r1s[tid], (double)r1q[tid]);
    }
}

// ---------------- finalize GN2 from fused partials ----------------
__global__ void finalize2_kernel(const double2* __restrict__ part2,
                                 const float* __restrict__ scale, const float* __restrict__ bias,
                                 float* __restrict__ aOut, float* __restrict__ dOut)
{
    const int idx = blockIdx.x;                 // lev*64 + b*8 + g
    const int lev = idx >> 6, b = (idx >> 3) & 7, g = idx & 7;
    const int cbS[5] = {0, 128, 160, 168, 170};
    const int Ls[4] = {16384, 4096, 1024, 256};

    double s = 0.0, ss = 0.0;
    for (int cb = cbS[lev]; cb < cbS[lev + 1]; ++cb) {
        double2 p = part2[(size_t)(b * NGROUP + g) * NCB + cb];
        s += p.x; ss += p.y;
    }
    const double cnt = 32.0 * (double)Ls[lev];
    const double mu = s / cnt;
    const float var = (float)(ss / cnt - mu * mu);
    const float rinv = rsqrtf(var + GNEPS);

    const int c = g * CPG + threadIdx.x;
    const float a = scale[c] * rinv;
    aOut[(lev * NBATCH + b) * CFEAT + c] = a;
    dOut[(lev * NBATCH + b) * CFEAT + c] = bias[c] - (float)mu * a;
}

// ---------------- stage 4: fused GN2-affine + ReLU + W2 dot + b2 -> logits ----------------
__global__ __launch_bounds__(256)
void logits_kernel(const float* __restrict__ h, const float* __restrict__ a2,
                   const float* __restrict__ d2, const float* __restrict__ W2,
                   const float* __restrict__ b2, float* __restrict__ logits,
                   float* __restrict__ outLog, int colOff)
{
    __shared__ float sa[256], sd[256], sw[256];
    const int tid = threadIdx.x;
    const int b = blockIdx.y;
    sa[tid] = a2[b * 256 + tid];
    sd[tid] = d2[b * 256 + tid];
    sw[tid] = W2[tid];
    __syncthreads();

    const int pos = colOff + blockIdx.x * 256 + tid;
    const float* hp = h + (size_t)b * 256 * NTOT + pos;
    float acc = b2[0];
#pragma unroll 8
    for (int c = 0; c < 256; ++c) {
        float v = hp[(size_t)c * NTOT];
        acc = fmaf(sw[c], fmaxf(fmaf(sa[c], v, sd[c]), 0.f), acc);
    }
    logits[b * NTOT + pos] = acc;
    if (outLog) outLog[b * NTOT + pos] = acc;
}

// ---------------- stage 5: top-100, packed 64-bit keys + warp shuffle ----------------
__global__ __launch_bounds__(1024)
void topk_kernel(const float* __restrict__ logits, float* __restrict__ outF, int* __restrict__ outI)
{
    extern __shared__ float sv[];
    __shared__ unsigned long long warpMax[32];
    const int b = blockIdx.x, tid = threadIdx.x;
    const int lane = tid & 31, wid = tid >> 5;
    const float NEGINF = __int_as_float(0xff800000);

    for (int i = tid; i < NTOT; i += 1024) sv[i] = logits[b * NTOT + i];
    __syncthreads();

    for (int k = 0; k < KTOP; ++k) {
        unsigned long long best = 0ull;
        for (int i = tid; i < NTOT; i += 1024) {
            unsigned u = __float_as_uint(sv[i]);
            u = (u & 0x80000000u) ? ~u : (u | 0x80000000u);   // order-preserving map
            unsigned long long key = ((unsigned long long)u << 32) | (unsigned)(NTOT - i);
            best = (key > best) ? key : best;
        }
#pragma unroll
        for (int off = 16; off; off >>= 1) {
            unsigned long long o = __shfl_down_sync(0xffffffffu, best, off);
            best = (o > best) ? o : best;
        }
        if (lane == 0) warpMax[wid] = best;
        __syncthreads();
        if (wid == 0) {
            unsigned long long v = warpMax[lane];
#pragma unroll
            for (int off = 16; off; off >>= 1) {
                unsigned long long o = __shfl_down_sync(0xffffffffu, v, off);
                v = (o > v) ? o : v;
            }
            if (lane == 0) {
                const int w = NTOT - (int)(v & 0xffffffffu);
                if (outF) outF[b * KTOP + k] = (float)w;
                if (outI) outI[b * KTOP + k] = w;
                sv[w] = NEGINF;
            }
        }
        __syncthreads();
    }
}

// ---------------- host launcher ----------------
extern "C" void kernel_launch(void* const* d_in, const int* in_sizes, int n_in,
                              void* d_out, int out_size)
{
    (void)in_sizes; (void)n_in;
    const float* xs[4] = {(const float*)d_in[0], (const float*)d_in[1],
                          (const float*)d_in[2], (const float*)d_in[3]};
    const float* gn1_scale = (const float*)d_in[4];
    const float* gn1_bias  = (const float*)d_in[5];
    const float* W1        = (const float*)d_in[6];
    const float* b1        = (const float*)d_in[7];
    const float* gn2_scale = (const float*)d_in[8];
    const float* gn2_bias  = (const float*)d_in[9];
    const float* W2        = (const float*)d_in[10];
    const float* b2        = (const float*)d_in[11];

    const int Ls[4]   = {16384, 4096, 1024, 256};
    const int offs[4] = {0, 16384, 20480, 21504};

    void* tmp;
    cudaGetSymbolAddress(&tmp, g_h);      float*   p_h     = (float*)tmp;
    cudaGetSymbolAddress(&tmp, g_logits); float*   p_log   = (float*)tmp;
    cudaGetSymbolAddress(&tmp, g_part1);  double2* p_part1 = (double2*)tmp;
    cudaGetSymbolAddress(&tmp, g_part2);  double2* p_part2 = (double2*)tmp;
    cudaGetSymbolAddress(&tmp, g_a1);     float*   p_a1    = (float*)tmp;
    cudaGetSymbolAddress(&tmp, g_d1);     float*   p_d1    = (float*)tmp;
    cudaGetSymbolAddress(&tmp, g_a2);     float*   p_a2    = (float*)tmp;
    cudaGetSymbolAddress(&tmp, g_d2);     float*   p_d2    = (float*)tmp;

    float* outF   = (float*)d_out;
    float* outLog = nullptr;
    float* outIdF = nullptr;
    int*   outIdI = nullptr;
    const int NIDS = NBATCH * KTOP;
    const int NLOG = NBATCH * NTOT;
    if (out_size >= NIDS + NLOG)      { outIdF = outF; outLog = outF + NIDS; }
    else if (out_size == NLOG)        { outLog = outF; }
    else if (out_size == NIDS)        { outIdI = (int*)d_out; }
    else                              { outIdF = outF; if (out_size > NIDS) outLog = outF + NIDS; }

    // 1) GN1 stats on x
    for (int lev = 0; lev < 4; ++lev) {
        const int nch = (Ls[lev] + 2047) / 2048;
        const int chunkL = Ls[lev] / nch;
        stats_kernel<<<dim3(nch, NGROUP, NBATCH), 256>>>(xs[lev], Ls[lev], chunkL,
                                                         p_part1, lev * 512);
    }
    finalize1_kernel<<<NLEV * NBATCH * NGROUP, 32>>>(p_part1, gn1_scale, gn1_bias, p_a1, p_d1);

    // 2) fused GN1+ReLU+GEMM1 (FFMA2) + bias + GN2 partial stats -> h
    for (int lev = 0; lev < 4; ++lev) {
        gemm1_kernel<<<dim3(Ls[lev] / 128, 2, NBATCH), 256>>>(
            xs[lev], W1, b1, p_a1 + lev * NBATCH * CFEAT, p_d1 + lev * NBATCH * CFEAT,
            p_h, p_part2, Ls[lev], offs[lev], offs[lev] / 128);
    }

    // 3) finalize GN2
    finalize2_kernel<<<NLEV * NBATCH * NGROUP, 32>>>(p_part2, gn2_scale, gn2_bias, p_a2, p_d2);

    // 4) logits
    for (int lev = 0; lev < 4; ++lev) {
        logits_kernel<<<dim3(Ls[lev] / 256, NBATCH), 256>>>(
            p_h, p_a2 + lev * NBATCH * CFEAT, p_d2 + lev * NBATCH * CFEAT,
            W2, b2, p_log, outLog, offs[lev]);
    }

    // 5) top-k
    cudaFuncSetAttribute(topk_kernel, cudaFuncAttributeMaxDynamicSharedMemorySize, NTOT * 4);
    topk_kernel<<<NBATCH, 1024, NTOT * 4>>>(p_log, outIdF, outIdI);
}

// round 3
// speedup vs baseline: 1.3157x; 1.0760x over previous
#include <cuda_runtime.h>
#include <cstdint>
#include <cstddef>

#define NBATCH 8
#define CFEAT  256
#define NGROUP 8
#define CPG    32
#define NTOT   21760
#define KTOP   100
#define NLEV   4
#define GNEPS  1e-5f
#define NCB    170
#define NSEG   680          // 21760 / 32

// ---------------- device scratch ----------------
__device__ float   g_h[(size_t)NBATCH * CFEAT * NTOT];
__device__ float   g_logits[NBATCH * NTOT];
__device__ double2 g_part1[NLEV * NBATCH * NGROUP * 8];
__device__ double2 g_part2[NBATCH * NGROUP * NCB];
__device__ float   g_a1[NLEV * NBATCH * CFEAT];
__device__ float   g_d1[NLEV * NBATCH * CFEAT];
__device__ float   g_a2[NLEV * NBATCH * CFEAT];
__device__ float   g_d2[NLEV * NBATCH * CFEAT];

// ---------------- packed f32x2 helpers ----------------
__device__ __forceinline__ void ffma2(unsigned long long& d, unsigned long long a,
                                      unsigned long long b) {
    asm("fma.rn.f32x2 %0, %1, %2, %0;" : "+l"(d) : "l"(a), "l"(b));
}
__device__ __forceinline__ float2 unpack2(unsigned long long v) {
    float2 r;
    asm("mov.b64 {%0,%1}, %2;" : "=f"(r.x), "=f"(r.y) : "l"(v));
    return r;
}
__device__ __forceinline__ unsigned long long swap2(unsigned long long v) {
    unsigned long long r;
    asm("{ .reg .b32 lo, hi;\n\t mov.b64 {lo,hi}, %1;\n\t mov.b64 %0, {hi,lo}; }"
        : "=l"(r) : "l"(v));
    return r;
}

// ---------------- GN1 stats: single merged launch, all levels ----------------
__global__ __launch_bounds__(256)
void stats_all_kernel(const float* __restrict__ x0, const float* __restrict__ x1,
                      const float* __restrict__ x2, const float* __restrict__ x3,
                      double2* __restrict__ part1)
{
    // block table: lev0: 512 blocks (nch=8), lev1: 128 (nch=2), lev2: 64, lev3: 64
    int bi = blockIdx.x;
    int lev, nchLog, L;
    const float* src;
    if (bi < 512)      { lev = 0; nchLog = 3; L = 16384; src = x0; }
    else if (bi < 640) { lev = 1; nchLog = 1; L = 4096;  src = x1; bi -= 512; }
    else if (bi < 704) { lev = 2; nchLog = 0; L = 1024;  src = x2; bi -= 640; }
    else               { lev = 3; nchLog = 0; L = 256;   src = x3; bi -= 704; }
    const int nch = 1 << nchLog;
    const int ch = bi & (nch - 1);
    const int bg = bi >> nchLog;
    const int b = bg >> 3, g = bg & 7;
    const int chunk = L >> nchLog;
    const int q0 = (ch * chunk) >> 2;
    const int q1 = ((ch + 1) * chunk) >> 2;
    const int tid = threadIdx.x;

    float s = 0.f, q = 0.f;
    for (int c = 0; c < CPG; ++c) {
        const float4* row = (const float4*)(src + (size_t)(b * CFEAT + g * CPG + c) * L);
        for (int i = q0 + tid; i < q1; i += 256) {
            float4 v = row[i];
            s += (v.x + v.y) + (v.z + v.w);
            q += (v.x * v.x + v.y * v.y) + (v.z * v.z + v.w * v.w);
        }
    }
#pragma unroll
    for (int off = 16; off; off >>= 1) {
        s += __shfl_down_sync(0xffffffffu, s, off);
        q += __shfl_down_sync(0xffffffffu, q, off);
    }
    __shared__ float ws[8], wq[8];
    if ((tid & 31) == 0) { ws[tid >> 5] = s; wq[tid >> 5] = q; }
    __syncthreads();
    if (tid == 0) {
        double S = 0.0, Q = 0.0;
        for (int w = 0; w < 8; ++w) { S += (double)ws[w]; Q += (double)wq[w]; }
        part1[lev * 512 + (b * NGROUP + g) * 8 + ch] = make_double2(S, Q);
    }
}

__global__ void finalize1_kernel(const double2* __restrict__ part,
                                 const float* __restrict__ scale, const float* __restrict__ bias,
                                 float* __restrict__ aOut, float* __restrict__ dOut)
{
    const int idx = blockIdx.x;                 // lev*64 + b*8 + g
    const int lev = idx >> 6, b = (idx >> 3) & 7, g = idx & 7;
    const int nchs[4] = {8, 2, 1, 1};
    const int Ls[4] = {16384, 4096, 1024, 256};
    const int nch = nchs[lev];

    double s = 0.0, ss = 0.0;
    for (int ch = 0; ch < nch; ++ch) {
        double2 p = part[lev * 512 + (b * NGROUP + g) * 8 + ch];
        s += p.x; ss += p.y;
    }
    const double cnt = 32.0 * (double)Ls[lev];
    const double mu = s / cnt;
    const float var = (float)(ss / cnt - mu * mu);
    const float rinv = rsqrtf(var + GNEPS);

    const int c = g * CPG + threadIdx.x;
    const float a = scale[c] * rinv;
    aOut[(lev * NBATCH + b) * CFEAT + c] = a;
    dOut[(lev * NBATCH + b) * CFEAT + c] = bias[c] - (float)mu * a;
}

// ---------------- stage 2: fused GN1+ReLU + FFMA2 GEMM (swap trick) + bias + GN2 stats ----------------
__global__ __launch_bounds__(256, 2)
void gemm1_kernel(const float* __restrict__ x, const float* __restrict__ W1,
                  const float* __restrict__ b1,
                  const float* __restrict__ a1, const float* __restrict__ d1,
                  float* __restrict__ hbase, double2* __restrict__ part2,
                  int L, int colOff, int colBase)
{
    __shared__ float As[2][8][128];
    __shared__ float Bs[2][8][128];
    __shared__ float sa[256], sd[256];
    __shared__ float redS[8], redQ[8];

    const int tid = threadIdx.x;
    const int b   = blockIdx.z;
    const int om2 = blockIdx.y;
    const int om  = om2 * 128;
    const int ln  = blockIdx.x * 128;

    sa[tid] = a1[b * 256 + tid];
    sd[tid] = d1[b * 256 + tid];

    const float* xb = x + (size_t)b * 256 * L;

    const int am = tid >> 1;
    const int ak = (tid & 1) * 4;
    const int bk = tid >> 5;
    const int bn = (tid & 31) * 4;
    const int ty = tid >> 4;
    const int tx = tid & 15;

    // acc0[mp][np] = (m0*n0, m1*n1); acc1[mp][np] = (m0*n1, m1*n0)
    unsigned long long acc0[4][4], acc1[4][4];
#pragma unroll
    for (int i = 0; i < 4; ++i)
#pragma unroll
        for (int j = 0; j < 4; ++j) { acc0[i][j] = 0ull; acc1[i][j] = 0ull; }

    __syncthreads();

    {
        float4 w = *(const float4*)&W1[(om + am) * 256 + ak];
        float4 v = *(const float4*)&xb[(size_t)bk * L + ln + bn];
        float a = sa[bk], d = sd[bk];
        As[0][ak + 0][am] = w.x; As[0][ak + 1][am] = w.y;
        As[0][ak + 2][am] = w.z; As[0][ak + 3][am] = w.w;
        float4 t = make_float4(fmaxf(fmaf(a, v.x, d), 0.f), fmaxf(fmaf(a, v.y, d), 0.f),
                               fmaxf(fmaf(a, v.z, d), 0.f), fmaxf(fmaf(a, v.w, d), 0.f));
        *(float4*)&Bs[0][bk][bn] = t;
    }
    __syncthreads();

    for (int kt = 0; kt < 32; ++kt) {
        const int cur = kt & 1;
        float4 wn, vn; float an = 0.f, dn = 0.f;
        if (kt < 31) {
            const int kc = (kt + 1) * 8;
            wn = *(const float4*)&W1[(om + am) * 256 + kc + ak];
            vn = *(const float4*)&xb[(size_t)(kc + bk) * L + ln + bn];
            an = sa[kc + bk]; dn = sd[kc + bk];
        }
#pragma unroll
        for (int kk = 0; kk < 8; ++kk) {
            ulonglong2 aA = *reinterpret_cast<const ulonglong2*>(&As[cur][kk][ty * 8]);
            ulonglong2 aB = *reinterpret_cast<const ulonglong2*>(&As[cur][kk][ty * 8 + 4]);
            ulonglong2 bA = *reinterpret_cast<const ulonglong2*>(&Bs[cur][kk][tx * 8]);
            ulonglong2 bB = *reinterpret_cast<const ulonglong2*>(&Bs[cur][kk][tx * 8 + 4]);
            unsigned long long av[4] = {aA.x, aA.y, aB.x, aB.y};
            unsigned long long bv[4] = {bA.x, bA.y, bB.x, bB.y};
            unsigned long long bs[4];
#pragma unroll
            for (int j = 0; j < 4; ++j) bs[j] = swap2(bv[j]);
#pragma unroll
            for (int mp = 0; mp < 4; ++mp)
#pragma unroll
                for (int np = 0; np < 4; ++np) {
                    ffma2(acc0[mp][np], av[mp], bv[np]);
                    ffma2(acc1[mp][np], av[mp], bs[np]);
                }
        }
        if (kt < 31) {
            const int nxt = cur ^ 1;
            As[nxt][ak + 0][am] = wn.x; As[nxt][ak + 1][am] = wn.y;
            As[nxt][ak + 2][am] = wn.z; As[nxt][ak + 3][am] = wn.w;
            float4 t = make_float4(fmaxf(fmaf(an, vn.x, dn), 0.f), fmaxf(fmaf(an, vn.y, dn), 0.f),
                                   fmaxf(fmaf(an, vn.z, dn), 0.f), fmaxf(fmaf(an, vn.w, dn), 0.f));
            *(float4*)&Bs[nxt][bk][bn] = t;
        }
        __syncthreads();
    }

    // epilogue: +bias, unscramble pairs, write h, per-thread group stats
    float* hrow = hbase + ((size_t)(b * 256 + om)) * NTOT + colOff + ln;
    float s = 0.f, q = 0.f;
#pragma unroll
    for (int mp = 0; mp < 4; ++mp) {
        const int r0 = ty * 8 + 2 * mp, r1 = r0 + 1;
        const float bb0 = b1[om + r0], bb1 = b1[om + r1];
        float2 c0[4], c1[4];
#pragma unroll
        for (int np = 0; np < 4; ++np) { c0[np] = unpack2(acc0[mp][np]); c1[np] = unpack2(acc1[mp][np]); }
        float v0[8] = {c0[0].x + bb0, c1[0].x + bb0, c0[1].x + bb0, c1[1].x + bb0,
                       c0[2].x + bb0, c1[2].x + bb0, c0[3].x + bb0, c1[3].x + bb0};
        float v1[8] = {c1[0].y + bb1, c0[0].y + bb1, c1[1].y + bb1, c0[1].y + bb1,
                       c1[2].y + bb1, c0[2].y + bb1, c1[3].y + bb1, c0[3].y + bb1};
        *(float4*)&hrow[(size_t)r0 * NTOT + tx * 8]     = make_float4(v0[0], v0[1], v0[2], v0[3]);
        *(float4*)&hrow[(size_t)r0 * NTOT + tx * 8 + 4] = make_float4(v0[4], v0[5], v0[6], v0[7]);
        *(float4*)&hrow[(size_t)r1 * NTOT + tx * 8]     = make_float4(v1[0], v1[1], v1[2], v1[3]);
        *(float4*)&hrow[(size_t)r1 * NTOT + tx * 8 + 4] = make_float4(v1[4], v1[5], v1[6], v1[7]);
#pragma unroll
        for (int j = 0; j < 8; ++j) {
            s += v0[j] + v1[j];
            q += v0[j] * v0[j] + v1[j] * v1[j];
        }
    }
    // all 8 rows of a thread lie in group (ty>>2); constant within a warp
#pragma unroll
    for (int off = 16; off; off >>= 1) {
        s += __shfl_down_sync(0xffffffffu, s, off);
        q += __shfl_down_sync(0xffffffffu, q, off);
    }
    const int wid = tid >> 5;
    if ((tid & 31) == 0) { redS[wid] = s; redQ[wid] = q; }
    __syncthreads();
    if (tid < 4) {
        const int cb = colBase + blockIdx.x;
        const int g = om2 * 4 + tid;
        const double S = (double)redS[2 * tid] + (double)redS[2 * tid + 1];
        const double Q = (double)redQ[2 * tid] + (double)redQ[2 * tid + 1];
        part2[(size_t)(b * NGROUP + g) * NCB + cb] = make_double2(S, Q);
    }
}

// ---------------- finalize GN2 ----------------
__global__ void finalize2_kernel(const double2* __restrict__ part2,
                                 const float* __restrict__ scale, const float* __restrict__ bias,
                                 float* __restrict__ aOut, float* __restrict__ dOut)
{
    const int idx = blockIdx.x;
    const int lev = idx >> 6, b = (idx >> 3) & 7, g = idx & 7;
    const int cbS[5] = {0, 128, 160, 168, 170};
    const int Ls[4] = {16384, 4096, 1024, 256};

    double s = 0.0, ss = 0.0;
    for (int cb = cbS[lev]; cb < cbS[lev + 1]; ++cb) {
        double2 p = part2[(size_t)(b * NGROUP + g) * NCB + cb];
        s += p.x; ss += p.y;
    }
    const double cnt = 32.0 * (double)Ls[lev];
    const double mu = s / cnt;
    const float var = (float)(ss / cnt - mu * mu);
    const float rinv = rsqrtf(var + GNEPS);

    const int c = g * CPG + threadIdx.x;
    const float a = scale[c] * rinv;
    aOut[(lev * NBATCH + b) * CFEAT + c] = a;
    dOut[(lev * NBATCH + b) * CFEAT + c] = bias[c] - (float)mu * a;
}

// ---------------- stage 4: GN2-affine + ReLU + W2 dot + b2 -> logits (float4) ----------------
__global__ __launch_bounds__(256)
void logits_kernel(const float* __restrict__ h, const float* __restrict__ a2,
                   const float* __restrict__ d2, const float* __restrict__ W2,
                   const float* __restrict__ b2, float* __restrict__ logits,
                   float* __restrict__ outLog, int colOff, int L)
{
    __shared__ float sa[256], sd[256], sw[256];
    const int tid = threadIdx.x;
    const int b = blockIdx.y;
    sa[tid] = a2[b * 256 + tid];
    sd[tid] = d2[b * 256 + tid];
    sw[tid] = W2[tid];
    __syncthreads();

    const int rel = blockIdx.x * 1024 + tid * 4;
    if (rel >= L) return;
    const int pos = colOff + rel;
    const float* hp = h + (size_t)b * 256 * NTOT + pos;
    const float bb = b2[0];
    float4 acc = make_float4(bb, bb, bb, bb);
#pragma unroll 4
    for (int c = 0; c < 256; ++c) {
        float4 v = *(const float4*)&hp[(size_t)c * NTOT];
        const float w = sw[c], a = sa[c], d = sd[c];
        acc.x = fmaf(w, fmaxf(fmaf(a, v.x, d), 0.f), acc.x);
        acc.y = fmaf(w, fmaxf(fmaf(a, v.y, d), 0.f), acc.y);
        acc.z = fmaf(w, fmaxf(fmaf(a, v.z, d), 0.f), acc.z);
        acc.w = fmaf(w, fmaxf(fmaf(a, v.w, d), 0.f), acc.w);
    }
    *(float4*)&logits[b * NTOT + pos] = acc;
    if (outLog) *(float4*)&outLog[b * NTOT + pos] = acc;
}

// ---------------- stage 5: segmented top-100 ----------------
__device__ __forceinline__ unsigned ford(float f) {
    unsigned u = __float_as_uint(f);
    return (u & 0x80000000u) ? ~u : (u | 0x80000000u);
}

__global__ __launch_bounds__(1024)
void topk_kernel(const float* __restrict__ logits, float* __restrict__ outF, int* __restrict__ outI)
{
    extern __shared__ float sv[];                 // [NTOT] values, then [NSEG] segment maxima
    float* segMax = sv + NTOT;
    __shared__ unsigned long long warpRes[32];
    __shared__ int winSeg;
    const int b = blockIdx.x, tid = threadIdx.x;
    const int lane = tid & 31, wid = tid >> 5;
    const float NEGINF = __int_as_float(0xff800000);

    for (int i = tid; i < NTOT; i += 1024) sv[i] = logits[b * NTOT + i];
    __syncthreads();
    if (tid < NSEG) {
        float m = NEGINF;
        for (int j = 0; j < 32; ++j) m = fmaxf(m, sv[tid * 32 + j]);
        segMax[tid] = m;
    }
    __syncthreads();

    for (int k = 0; k < KTOP; ++k) {
        // global scan of segment maxima
        unsigned long long key = 0ull;
        if (tid < NSEG)
            key = ((unsigned long long)ford(segMax[tid]) << 32) | (unsigned)(NSEG - 1 - tid);
#pragma unroll
        for (int off = 16; off; off >>= 1) {
            unsigned long long o = __shfl_down_sync(0xffffffffu, key, off);
            key = (o > key) ? o : key;
        }
        if (lane == 0) warpRes[wid] = key;
        __syncthreads();
        if (wid == 0) {
            unsigned long long v = warpRes[lane];
#pragma unroll
            for (int off = 16; off; off >>= 1) {
                unsigned long long o = __shfl_down_sync(0xffffffffu, v, off);
                v = (o > v) ? o : v;
            }
            if (lane == 0) winSeg = NSEG - 1 - (int)(v & 0xffffffffu);
        }
        __syncthreads();
        // warp 0 resolves within the winning segment, emits, and repairs segMax
        if (wid == 0) {
            const int s = winSeg;
            float v = sv[s * 32 + lane];
            unsigned long long k2 = ((unsigned long long)ford(v) << 32) | (unsigned)(31 - lane);
            unsigned long long r = k2;
#pragma unroll
            for (int off = 16; off; off >>= 1) {
                unsigned long long o = __shfl_xor_sync(0xffffffffu, r, off);
                r = (o > r) ? o : r;
            }
            const int wl = 31 - (int)(r & 31u);
            if (lane == wl) {
                const int idx = s * 32 + wl;
                if (outF) outF[b * KTOP + k] = (float)idx;
                if (outI) outI[b * KTOP + k] = idx;
                sv[idx] = NEGINF;
                v = NEGINF;
            }
            float m = v;
#pragma unroll
            for (int off = 16; off; off >>= 1)
                m = fmaxf(m, __shfl_xor_sync(0xffffffffu, m, off));
            if (lane == 0) segMax[s] = m;
        }
        __syncthreads();
    }
}

// ---------------- host launcher ----------------
extern "C" void kernel_launch(void* const* d_in, const int* in_sizes, int n_in,
                              void* d_out, int out_size)
{
    (void)in_sizes; (void)n_in;
    const float* xs[4] = {(const float*)d_in[0], (const float*)d_in[1],
                          (const float*)d_in[2], (const float*)d_in[3]};
    const float* gn1_scale = (const float*)d_in[4];
    const float* gn1_bias  = (const float*)d_in[5];
    const float* W1        = (const float*)d_in[6];
    const float* b1        = (const float*)d_in[7];
    const float* gn2_scale = (const float*)d_in[8];
    const float* gn2_bias  = (const float*)d_in[9];
    const float* W2        = (const float*)d_in[10];
    const float* b2        = (const float*)d_in[11];

    const int Ls[4]   = {16384, 4096, 1024, 256};
    const int offs[4] = {0, 16384, 20480, 21504};

    void* tmp;
    cudaGetSymbolAddress(&tmp, g_h);      float*   p_h     = (float*)tmp;
    cudaGetSymbolAddress(&tmp, g_logits); float*   p_log   = (float*)tmp;
    cudaGetSymbolAddress(&tmp, g_part1);  double2* p_part1 = (double2*)tmp;
    cudaGetSymbolAddress(&tmp, g_part2);  double2* p_part2 = (double2*)tmp;
    cudaGetSymbolAddress(&tmp, g_a1);     float*   p_a1    = (float*)tmp;
    cudaGetSymbolAddress(&tmp, g_d1);     float*   p_d1    = (float*)tmp;
    cudaGetSymbolAddress(&tmp, g_a2);     float*   p_a2    = (float*)tmp;
    cudaGetSymbolAddress(&tmp, g_d2);     float*   p_d2    = (float*)tmp;

    float* outF   = (float*)d_out;
    float* outLog = nullptr;
    float* outIdF = nullptr;
    int*   outIdI = nullptr;
    const int NIDS = NBATCH * KTOP;
    const int NLOG = NBATCH * NTOT;
    if (out_size >= NIDS + NLOG)      { outIdF = outF; outLog = outF + NIDS; }
    else if (out_size == NLOG)        { outLog = outF; }
    else if (out_size == NIDS)        { outIdI = (int*)d_out; }
    else                              { outIdF = outF; if (out_size > NIDS) outLog = outF + NIDS; }

    // 1) GN1 stats (single launch, all levels)
    stats_all_kernel<<<768, 256>>>(xs[0], xs[1], xs[2], xs[3], p_part1);
    finalize1_kernel<<<NLEV * NBATCH * NGROUP, 32>>>(p_part1, gn1_scale, gn1_bias, p_a1, p_d1);

    // 2) fused GN1+ReLU+GEMM1 + bias + GN2 partial stats -> h
    for (int lev = 0; lev < 4; ++lev) {
        gemm1_kernel<<<dim3(Ls[lev] / 128, 2, NBATCH), 256>>>(
            xs[lev], W1, b1, p_a1 + lev * NBATCH * CFEAT, p_d1 + lev * NBATCH * CFEAT,
            p_h, p_part2, Ls[lev], offs[lev], offs[lev] / 128);
    }

    // 3) finalize GN2
    finalize2_kernel<<<NLEV * NBATCH * NGROUP, 32>>>(p_part2, gn2_scale, gn2_bias, p_a2, p_d2);

    // 4) logits
    for (int lev = 0; lev < 4; ++lev) {
        const int nblk = (Ls[lev] + 1023) / 1024;
        logits_kernel<<<dim3(nblk, NBATCH), 256>>>(
            p_h, p_a2 + lev * NBATCH * CFEAT, p_d2 + lev * NBATCH * CFEAT,
            W2, b2, p_log, outLog, offs[lev], Ls[lev]);
    }

    // 5) segmented top-k
    const int tkSmem = (NTOT + NSEG) * 4;
    cudaFuncSetAttribute(topk_kernel, cudaFuncAttributeMaxDynamicSharedMemorySize, tkSmem);
    topk_kernel<<<NBATCH, 1024, tkSmem>>>(p_log, outIdF, outIdI);
}